// round 1
// baseline (speedup 1.0000x reference)
#include <cuda_runtime.h>

// Quanvolution quantum filter: N = 8192*196 independent 4-qubit real
// statevector sims, one thread per patch, state fully in registers.

#define BATCH   8192
#define NPATCH  196
#define NTOT    (BATCH * NPATCH)

__global__ __launch_bounds__(256)
void quanv_kernel(const float* __restrict__ x,
                  const float* __restrict__ params,
                  float* __restrict__ out)
{
    // Per-block precompute of the 8 parameter (cos, sin) pairs.
    __shared__ float pc[8], ps[8];
    if (threadIdx.x < 8) {
        float s, c;
        __sincosf(0.5f * params[threadIdx.x], &s, &c);
        pc[threadIdx.x] = c;
        ps[threadIdx.x] = s;
    }
    __syncthreads();

    int n = blockIdx.x * blockDim.x + threadIdx.x;
    if (n >= NTOT) return;

    int b = n / NPATCH;
    int p = n - b * NPATCH;
    int r = p / 14;
    int c = p - r * 14;

    const float* img = x + b * 784;
    float2 top = *reinterpret_cast<const float2*>(img + (2 * r) * 28 + 2 * c);
    float2 bot = *reinterpret_cast<const float2*>(img + (2 * r + 1) * 28 + 2 * c);

    // angles: [TL, TR, BL, BR] -> wires 0..3
    float s0, c0, s1, c1, s2, c2, s3, c3;
    __sincosf(0.5f * top.x, &s0, &c0);
    __sincosf(0.5f * top.y, &s1, &c1);
    __sincosf(0.5f * bot.x, &s2, &c2);
    __sincosf(0.5f * bot.y, &s3, &c3);

    // Product state after initial RYs: st[b0*8 + b1*4 + b2*2 + b3]
    // = f0(b0) f1(b1) f2(b2) f3(b3), f(0)=cos, f(1)=sin.
    float a00 = c0 * c1, a01 = c0 * s1, a10 = s0 * c1, a11 = s0 * s1;
    float b00 = c2 * c3, b01 = c2 * s3, b10 = s2 * c3, b11 = s2 * s3;

    float st[16];
    st[ 0] = a00 * b00; st[ 1] = a00 * b01; st[ 2] = a00 * b10; st[ 3] = a00 * b11;
    st[ 4] = a01 * b00; st[ 5] = a01 * b01; st[ 6] = a01 * b10; st[ 7] = a01 * b11;
    st[ 8] = a10 * b00; st[ 9] = a10 * b01; st[10] = a10 * b10; st[11] = a10 * b11;
    st[12] = a11 * b00; st[13] = a11 * b01; st[14] = a11 * b10; st[15] = a11 * b11;

    #pragma unroll
    for (int l = 0; l < 2; ++l) {
        // RY(params[l][w]) on wire w (index bit = 3 - w)
        #pragma unroll
        for (int w = 0; w < 4; ++w) {
            float cc = pc[l * 4 + w], ss = ps[l * 4 + w];
            int m = 8 >> w;
            #pragma unroll
            for (int i = 0; i < 16; ++i) {
                if (!(i & m)) {
                    float A = st[i], B = st[i | m];
                    st[i]     = cc * A - ss * B;
                    st[i | m] = ss * A + cc * B;
                }
            }
        }
        // CNOT(0,1): ctrl mask 8, tgt mask 4
        #pragma unroll
        for (int i = 0; i < 16; ++i)
            if ((i & 8) && !(i & 4)) { float t = st[i]; st[i] = st[i | 4]; st[i | 4] = t; }
        // CNOT(1,2): ctrl mask 4, tgt mask 2
        #pragma unroll
        for (int i = 0; i < 16; ++i)
            if ((i & 4) && !(i & 2)) { float t = st[i]; st[i] = st[i | 2]; st[i | 2] = t; }
        // CNOT(2,3): ctrl mask 2, tgt mask 1
        #pragma unroll
        for (int i = 0; i < 16; ++i)
            if ((i & 2) && !(i & 1)) { float t = st[i]; st[i] = st[i | 1]; st[i | 1] = t; }
        // CNOT(3,0): ctrl mask 1, tgt mask 8
        #pragma unroll
        for (int i = 0; i < 16; ++i)
            if ((i & 1) && !(i & 8)) { float t = st[i]; st[i] = st[i | 8]; st[i | 8] = t; }
    }

    float pr[16];
    #pragma unroll
    for (int i = 0; i < 16; ++i) pr[i] = st[i] * st[i];

    // Signed reduction tree for <Z_q>.
    float e[8], z3 = 0.f;
    #pragma unroll
    for (int j = 0; j < 8; ++j) {
        e[j] = pr[2 * j] + pr[2 * j + 1];   // sum over bit0 (wire 3)
        z3  += pr[2 * j] - pr[2 * j + 1];
    }
    float f[4], z2 = 0.f;
    #pragma unroll
    for (int j = 0; j < 4; ++j) {
        f[j] = e[2 * j] + e[2 * j + 1];     // sum over bit1 (wire 2)
        z2  += e[2 * j] - e[2 * j + 1];
    }
    float z1 = (f[0] - f[1]) + (f[2] - f[3]);  // bit2 (wire 1)
    float z0 = (f[0] + f[1]) - (f[2] + f[3]);  // bit3 (wire 0)

    float4 o;
    o.x = z0; o.y = z1; o.z = z2; o.w = z3;
    reinterpret_cast<float4*>(out)[n] = o;
}

extern "C" void kernel_launch(void* const* d_in, const int* in_sizes, int n_in,
                              void* d_out, int out_size)
{
    const float* x      = (const float*)d_in[0];   // (8192,1,28,28) float32
    const float* params = (const float*)d_in[1];   // (2,4) float32
    float* out          = (float*)d_out;           // (8192, 784) float32

    (void)in_sizes; (void)n_in; (void)out_size;

    const int threads = 256;
    const int blocks  = (NTOT + threads - 1) / threads;  // 6272
    quanv_kernel<<<blocks, threads>>>(x, params, out);
}

// round 2
// speedup vs baseline: 1.1458x; 1.1458x over previous
#include <cuda_runtime.h>

// Quanvolution quantum filter, packed-f32x2 version:
// each thread simulates TWO adjacent patches with the two lanes of the
// sm_100+ packed float2 ALU (fma.rn.f32x2 / mul.rn.f32x2 / add.rn.f32x2).

#define BATCH   8192
#define NPATCH  196
#define NTOT    (BATCH * NPATCH)
#define NPAIR   (NTOT / 2)          // 802816 = 6272 * 128

typedef unsigned long long u64;

__device__ __forceinline__ u64 pk2(float lo, float hi) {
    u64 r; asm("mov.b64 %0, {%1, %2};" : "=l"(r) : "f"(lo), "f"(hi)); return r;
}
__device__ __forceinline__ u64 bc2(float v) { return pk2(v, v); }
__device__ __forceinline__ u64 mul2(u64 a, u64 b) {
    u64 r; asm("mul.rn.f32x2 %0, %1, %2;" : "=l"(r) : "l"(a), "l"(b)); return r;
}
__device__ __forceinline__ u64 fma2(u64 a, u64 b, u64 c) {
    u64 r; asm("fma.rn.f32x2 %0, %1, %2, %3;" : "=l"(r) : "l"(a), "l"(b), "l"(c)); return r;
}
__device__ __forceinline__ u64 add2(u64 a, u64 b) {
    u64 r; asm("add.rn.f32x2 %0, %1, %2;" : "=l"(r) : "l"(a), "l"(b)); return r;
}
__device__ __forceinline__ void upk2(u64 v, float& lo, float& hi) {
    asm("mov.b64 {%0, %1}, %2;" : "=f"(lo), "=f"(hi) : "l"(v));
}

__global__ __launch_bounds__(128)
void quanv2_kernel(const float* __restrict__ x,
                   const float* __restrict__ params,
                   float* __restrict__ out)
{
    __shared__ float pc[8], ps[8];
    if (threadIdx.x < 8) {
        float s, c;
        __sincosf(0.5f * params[threadIdx.x], &s, &c);
        pc[threadIdx.x] = c;
        ps[threadIdx.x] = s;
    }
    __syncthreads();

    int q = blockIdx.x * blockDim.x + threadIdx.x;   // pair index, no guard needed

    int b  = q / 98;                 // 98 patch-pairs per image
    int pp = q - b * 98;
    int r  = pp / 7;                 // patch row 0..13
    int j  = pp - r * 7;             // pair column; patches (2j, 2j+1)

    const float* img = x + b * 784;
    // Top/bottom image rows of both patches: 4 consecutive floats each.
    float4 top = *reinterpret_cast<const float4*>(img + (2 * r) * 28 + 4 * j);
    float4 bot = *reinterpret_cast<const float4*>(img + (2 * r + 1) * 28 + 4 * j);

    // Angles per patch: [TL, TR, BL, BR] -> wires 0..3
    float sA0, cA0, sA1, cA1, sA2, cA2, sA3, cA3;   // patch 0 (lo lane)
    float sB0, cB0, sB1, cB1, sB2, cB2, sB3, cB3;   // patch 1 (hi lane)
    __sincosf(0.5f * top.x, &sA0, &cA0);
    __sincosf(0.5f * top.y, &sA1, &cA1);
    __sincosf(0.5f * bot.x, &sA2, &cA2);
    __sincosf(0.5f * bot.y, &sA3, &cA3);
    __sincosf(0.5f * top.z, &sB0, &cB0);
    __sincosf(0.5f * top.w, &sB1, &cB1);
    __sincosf(0.5f * bot.z, &sB2, &cB2);
    __sincosf(0.5f * bot.w, &sB3, &cB3);

    // Product-state factors: A2[b0*2+b1], B2[b2*2+b3], packed across patches.
    u64 A2[4], B2[4];
    A2[0] = pk2(cA0 * cA1, cB0 * cB1);
    A2[1] = pk2(cA0 * sA1, cB0 * sB1);
    A2[2] = pk2(sA0 * cA1, sB0 * cB1);
    A2[3] = pk2(sA0 * sA1, sB0 * sB1);
    B2[0] = pk2(cA2 * cA3, cB2 * cB3);
    B2[1] = pk2(cA2 * sA3, cB2 * sB3);
    B2[2] = pk2(sA2 * cA3, sB2 * cB3);
    B2[3] = pk2(sA2 * sA3, sB2 * sB3);

    // st[b0*8 + b1*4 + b2*2 + b3]; wire w <-> bit (3-w).
    u64 st[16];
    #pragma unroll
    for (int i = 0; i < 16; ++i)
        st[i] = mul2(A2[i >> 2], B2[i & 3]);

    #pragma unroll
    for (int l = 0; l < 2; ++l) {
        #pragma unroll
        for (int w = 0; w < 4; ++w) {
            float cs = pc[l * 4 + w], ss = ps[l * 4 + w];
            u64 cc2  = bc2(cs);
            u64 ss2  = bc2(ss);
            u64 ssn2 = bc2(-ss);
            int m = 8 >> w;
            #pragma unroll
            for (int i = 0; i < 16; ++i) {
                if (!(i & m)) {
                    u64 A = st[i], B = st[i | m];
                    u64 t0 = mul2(ssn2, B);          // -ss*B
                    u64 t1 = mul2(cc2,  B);          //  cc*B
                    st[i]     = fma2(cc2, A, t0);    //  cc*A - ss*B
                    st[i | m] = fma2(ss2, A, t1);    //  ss*A + cc*B
                }
            }
        }
        // CNOT ring: pure register permutations (free).
        #pragma unroll
        for (int i = 0; i < 16; ++i)
            if ((i & 8) && !(i & 4)) { u64 t = st[i]; st[i] = st[i | 4]; st[i | 4] = t; }
        #pragma unroll
        for (int i = 0; i < 16; ++i)
            if ((i & 4) && !(i & 2)) { u64 t = st[i]; st[i] = st[i | 2]; st[i | 2] = t; }
        #pragma unroll
        for (int i = 0; i < 16; ++i)
            if ((i & 2) && !(i & 1)) { u64 t = st[i]; st[i] = st[i | 1]; st[i | 1] = t; }
        #pragma unroll
        for (int i = 0; i < 16; ++i)
            if ((i & 1) && !(i & 8)) { u64 t = st[i]; st[i] = st[i | 8]; st[i | 8] = t; }
    }

    // Probabilities (in place).
    #pragma unroll
    for (int i = 0; i < 16; ++i)
        st[i] = mul2(st[i], st[i]);

    u64 NEG = bc2(-1.0f);

    // Z3 (bit0) + partial sums over bit0.
    u64 e[8], d3[8];
    #pragma unroll
    for (int k = 0; k < 8; ++k) {
        e[k]  = add2(st[2 * k], st[2 * k + 1]);
        d3[k] = fma2(NEG, st[2 * k + 1], st[2 * k]);   // pr[2k] - pr[2k+1]
    }
    u64 z3 = add2(add2(add2(d3[0], d3[1]), add2(d3[2], d3[3])),
                  add2(add2(d3[4], d3[5]), add2(d3[6], d3[7])));

    // Z2 (bit1) + partial sums over bit1.
    u64 f[4], d2[4];
    #pragma unroll
    for (int k = 0; k < 4; ++k) {
        f[k]  = add2(e[2 * k], e[2 * k + 1]);
        d2[k] = fma2(NEG, e[2 * k + 1], e[2 * k]);
    }
    u64 z2 = add2(add2(d2[0], d2[1]), add2(d2[2], d2[3]));

    // Z1 (bit2), Z0 (bit3).
    u64 z1 = add2(fma2(NEG, f[1], f[0]), fma2(NEG, f[3], f[2]));
    u64 z0 = fma2(NEG, add2(f[2], f[3]), add2(f[0], f[1]));

    float4 o0, o1;
    upk2(z0, o0.x, o1.x);
    upk2(z1, o0.y, o1.y);
    upk2(z2, o0.z, o1.z);
    upk2(z3, o0.w, o1.w);

    int n0 = 2 * q;                           // global patch index of lo lane
    reinterpret_cast<float4*>(out)[n0]     = o0;
    reinterpret_cast<float4*>(out)[n0 + 1] = o1;
}

extern "C" void kernel_launch(void* const* d_in, const int* in_sizes, int n_in,
                              void* d_out, int out_size)
{
    const float* x      = (const float*)d_in[0];   // (8192,1,28,28) float32
    const float* params = (const float*)d_in[1];   // (2,4) float32
    float* out          = (float*)d_out;           // (8192, 784) float32

    (void)in_sizes; (void)n_in; (void)out_size;

    const int threads = 128;
    const int blocks  = NPAIR / threads;           // 6272, exact
    quanv2_kernel<<<blocks, threads>>>(x, params, out);
}

// round 3
// speedup vs baseline: 1.5570x; 1.3589x over previous
#include <cuda_runtime.h>

// Quanvolution quantum filter, packed-f32x2 + layer-0 fold:
// RY(param)·RY(data) on the same wire = RY(param+data), so layer 0's
// butterflies collapse into an angle shift. Circuit per patch:
//   product state (shifted angles) -> CNOT ring -> layer-1 RYs -> CNOT ring -> Z.
// Each thread simulates TWO adjacent patches via packed f32x2 ALU ops.

#define BATCH   8192
#define NPATCH  196
#define NTOT    (BATCH * NPATCH)
#define NPAIR   (NTOT / 2)          // 802816 = 6272 * 128

typedef unsigned long long u64;

__device__ __forceinline__ u64 pk2(float lo, float hi) {
    u64 r; asm("mov.b64 %0, {%1, %2};" : "=l"(r) : "f"(lo), "f"(hi)); return r;
}
__device__ __forceinline__ u64 bc2(float v) { return pk2(v, v); }
__device__ __forceinline__ u64 mul2(u64 a, u64 b) {
    u64 r; asm("mul.rn.f32x2 %0, %1, %2;" : "=l"(r) : "l"(a), "l"(b)); return r;
}
__device__ __forceinline__ u64 fma2(u64 a, u64 b, u64 c) {
    u64 r; asm("fma.rn.f32x2 %0, %1, %2, %3;" : "=l"(r) : "l"(a), "l"(b), "l"(c)); return r;
}
__device__ __forceinline__ u64 add2(u64 a, u64 b) {
    u64 r; asm("add.rn.f32x2 %0, %1, %2;" : "=l"(r) : "l"(a), "l"(b)); return r;
}
__device__ __forceinline__ void upk2(u64 v, float& lo, float& hi) {
    asm("mov.b64 {%0, %1}, %2;" : "=f"(lo), "=f"(hi) : "l"(v));
}

__global__ __launch_bounds__(128)
void quanv3_kernel(const float* __restrict__ x,
                   const float* __restrict__ params,
                   float* __restrict__ out)
{
    // ph: half of layer-0 params (folded into data angles).
    // pc/ps: cos/sin of half of layer-1 params.
    __shared__ float ph[4], pc[4], ps[4];
    if (threadIdx.x < 4) {
        ph[threadIdx.x] = 0.5f * params[threadIdx.x];
        float s, c;
        __sincosf(0.5f * params[4 + threadIdx.x], &s, &c);
        pc[threadIdx.x] = c;
        ps[threadIdx.x] = s;
    }
    __syncthreads();

    int q = blockIdx.x * blockDim.x + threadIdx.x;   // pair index (exact grid)

    int b  = q / 98;                 // 98 patch-pairs per image
    int pp = q - b * 98;
    int r  = pp / 7;                 // patch row 0..13
    int j  = pp - r * 7;             // pair column; patches (2j, 2j+1)

    const float* img = x + b * 784;
    float4 top = *reinterpret_cast<const float4*>(img + (2 * r) * 28 + 4 * j);
    float4 bot = *reinterpret_cast<const float4*>(img + (2 * r + 1) * 28 + 4 * j);

    float h0 = ph[0], h1 = ph[1], h2 = ph[2], h3 = ph[3];

    // Shifted half-angles per patch: 0.5*x + 0.5*param0  (wires 0..3)
    float sA0, cA0, sA1, cA1, sA2, cA2, sA3, cA3;   // patch 0 (lo lane)
    float sB0, cB0, sB1, cB1, sB2, cB2, sB3, cB3;   // patch 1 (hi lane)
    __sincosf(fmaf(0.5f, top.x, h0), &sA0, &cA0);
    __sincosf(fmaf(0.5f, top.y, h1), &sA1, &cA1);
    __sincosf(fmaf(0.5f, bot.x, h2), &sA2, &cA2);
    __sincosf(fmaf(0.5f, bot.y, h3), &sA3, &cA3);
    __sincosf(fmaf(0.5f, top.z, h0), &sB0, &cB0);
    __sincosf(fmaf(0.5f, top.w, h1), &sB1, &cB1);
    __sincosf(fmaf(0.5f, bot.z, h2), &sB2, &cB2);
    __sincosf(fmaf(0.5f, bot.w, h3), &sB3, &cB3);

    // Product-state factors (after data + layer-0 RYs).
    u64 A2[4], B2[4];
    A2[0] = pk2(cA0 * cA1, cB0 * cB1);
    A2[1] = pk2(cA0 * sA1, cB0 * sB1);
    A2[2] = pk2(sA0 * cA1, sB0 * cB1);
    A2[3] = pk2(sA0 * sA1, sB0 * sB1);
    B2[0] = pk2(cA2 * cA3, cB2 * cB3);
    B2[1] = pk2(cA2 * sA3, cB2 * sB3);
    B2[2] = pk2(sA2 * cA3, sB2 * cB3);
    B2[3] = pk2(sA2 * sA3, sB2 * sB3);

    // st[b0*8 + b1*4 + b2*2 + b3]; wire w <-> bit (3-w).
    u64 st[16];
    #pragma unroll
    for (int i = 0; i < 16; ++i)
        st[i] = mul2(A2[i >> 2], B2[i & 3]);

    // ---- layer 0 residual: CNOT ring (register permutation, free) ----
    #pragma unroll
    for (int i = 0; i < 16; ++i)
        if ((i & 8) && !(i & 4)) { u64 t = st[i]; st[i] = st[i | 4]; st[i | 4] = t; }
    #pragma unroll
    for (int i = 0; i < 16; ++i)
        if ((i & 4) && !(i & 2)) { u64 t = st[i]; st[i] = st[i | 2]; st[i | 2] = t; }
    #pragma unroll
    for (int i = 0; i < 16; ++i)
        if ((i & 2) && !(i & 1)) { u64 t = st[i]; st[i] = st[i | 1]; st[i | 1] = t; }
    #pragma unroll
    for (int i = 0; i < 16; ++i)
        if ((i & 1) && !(i & 8)) { u64 t = st[i]; st[i] = st[i | 8]; st[i | 8] = t; }

    // ---- layer 1: param RYs (the only remaining butterfly pass) ----
    #pragma unroll
    for (int w = 0; w < 4; ++w) {
        float cs = pc[w], ss = ps[w];
        u64 cc2  = bc2(cs);
        u64 ss2  = bc2(ss);
        u64 ssn2 = bc2(-ss);
        int m = 8 >> w;
        #pragma unroll
        for (int i = 0; i < 16; ++i) {
            if (!(i & m)) {
                u64 A = st[i], B = st[i | m];
                u64 t0 = mul2(ssn2, B);          // -ss*B
                u64 t1 = mul2(cc2,  B);          //  cc*B
                st[i]     = fma2(cc2, A, t0);    //  cc*A - ss*B
                st[i | m] = fma2(ss2, A, t1);    //  ss*A + cc*B
            }
        }
    }

    // ---- layer 1 CNOT ring (free) ----
    #pragma unroll
    for (int i = 0; i < 16; ++i)
        if ((i & 8) && !(i & 4)) { u64 t = st[i]; st[i] = st[i | 4]; st[i | 4] = t; }
    #pragma unroll
    for (int i = 0; i < 16; ++i)
        if ((i & 4) && !(i & 2)) { u64 t = st[i]; st[i] = st[i | 2]; st[i | 2] = t; }
    #pragma unroll
    for (int i = 0; i < 16; ++i)
        if ((i & 2) && !(i & 1)) { u64 t = st[i]; st[i] = st[i | 1]; st[i | 1] = t; }
    #pragma unroll
    for (int i = 0; i < 16; ++i)
        if ((i & 1) && !(i & 8)) { u64 t = st[i]; st[i] = st[i | 8]; st[i | 8] = t; }

    // ---- probabilities + signed reduction tree ----
    #pragma unroll
    for (int i = 0; i < 16; ++i)
        st[i] = mul2(st[i], st[i]);

    u64 NEG = bc2(-1.0f);

    u64 e[8], d3[8];
    #pragma unroll
    for (int k = 0; k < 8; ++k) {
        e[k]  = add2(st[2 * k], st[2 * k + 1]);
        d3[k] = fma2(NEG, st[2 * k + 1], st[2 * k]);   // pr[2k] - pr[2k+1]
    }
    u64 z3 = add2(add2(add2(d3[0], d3[1]), add2(d3[2], d3[3])),
                  add2(add2(d3[4], d3[5]), add2(d3[6], d3[7])));

    u64 f[4], d2[4];
    #pragma unroll
    for (int k = 0; k < 4; ++k) {
        f[k]  = add2(e[2 * k], e[2 * k + 1]);
        d2[k] = fma2(NEG, e[2 * k + 1], e[2 * k]);
    }
    u64 z2 = add2(add2(d2[0], d2[1]), add2(d2[2], d2[3]));

    u64 z1 = add2(fma2(NEG, f[1], f[0]), fma2(NEG, f[3], f[2]));
    u64 z0 = fma2(NEG, add2(f[2], f[3]), add2(f[0], f[1]));

    float4 o0, o1;
    upk2(z0, o0.x, o1.x);
    upk2(z1, o0.y, o1.y);
    upk2(z2, o0.z, o1.z);
    upk2(z3, o0.w, o1.w);

    int n0 = 2 * q;
    reinterpret_cast<float4*>(out)[n0]     = o0;
    reinterpret_cast<float4*>(out)[n0 + 1] = o1;
}

extern "C" void kernel_launch(void* const* d_in, const int* in_sizes, int n_in,
                              void* d_out, int out_size)
{
    const float* x      = (const float*)d_in[0];   // (8192,1,28,28) float32
    const float* params = (const float*)d_in[1];   // (2,4) float32
    float* out          = (float*)d_out;           // (8192, 784) float32

    (void)in_sizes; (void)n_in; (void)out_size;

    const int threads = 128;
    const int blocks  = NPAIR / threads;           // 6272, exact
    quanv3_kernel<<<blocks, threads>>>(x, params, out);
}

// round 5
// speedup vs baseline: 1.5806x; 1.0152x over previous
#include <cuda_runtime.h>

// Quanvolution quantum filter:
//  - layer-0 RYs folded into data angles (RY(p)RY(x) = RY(p+x))
//  - two patches per thread via packed f32x2 ALU ops
//  - layer-1 butterflies via 3-shear lifting (3 FMA per 2x2 rotation)
//    rotation angle of the butterfly is phi = theta/2, so the lifting
//    constants are t = tan(theta/4), s = sin(theta/2).

#define BATCH   8192
#define NPATCH  196
#define NTOT    (BATCH * NPATCH)
#define NPAIR   (NTOT / 2)          // 802816 = 6272 * 128

typedef unsigned long long u64;

__device__ __forceinline__ u64 pk2(float lo, float hi) {
    u64 r; asm("mov.b64 %0, {%1, %2};" : "=l"(r) : "f"(lo), "f"(hi)); return r;
}
__device__ __forceinline__ u64 bc2(float v) { return pk2(v, v); }
__device__ __forceinline__ u64 mul2(u64 a, u64 b) {
    u64 r; asm("mul.rn.f32x2 %0, %1, %2;" : "=l"(r) : "l"(a), "l"(b)); return r;
}
__device__ __forceinline__ u64 fma2(u64 a, u64 b, u64 c) {
    u64 r; asm("fma.rn.f32x2 %0, %1, %2, %3;" : "=l"(r) : "l"(a), "l"(b), "l"(c)); return r;
}
__device__ __forceinline__ u64 add2(u64 a, u64 b) {
    u64 r; asm("add.rn.f32x2 %0, %1, %2;" : "=l"(r) : "l"(a), "l"(b)); return r;
}
__device__ __forceinline__ void upk2(u64 v, float& lo, float& hi) {
    asm("mov.b64 {%0, %1}, %2;" : "=f"(lo), "=f"(hi) : "l"(v));
}

__global__ __launch_bounds__(128)
void quanv5_kernel(const float* __restrict__ x,
                   const float* __restrict__ params,
                   float* __restrict__ out)
{
    // ph: half of layer-0 params (folded into data angles).
    // pt: tan(theta/4), psn: sin(theta/2) for layer-1 lifting.
    __shared__ float ph[4], pt[4], psn[4];
    if (threadIdx.x < 4) {
        ph[threadIdx.x] = 0.5f * params[threadIdx.x];
        float th = params[4 + threadIdx.x];
        float s4, c4;
        __sincosf(0.25f * th, &s4, &c4);
        pt[threadIdx.x]  = s4 / c4;              // tan(theta/4)
        psn[threadIdx.x] = 2.0f * s4 * c4;       // sin(theta/2)
    }
    __syncthreads();

    int q = blockIdx.x * blockDim.x + threadIdx.x;   // pair index (exact grid)

    int b  = q / 98;                 // 98 patch-pairs per image
    int pp = q - b * 98;
    int r  = pp / 7;                 // patch row 0..13
    int j  = pp - r * 7;             // pair column; patches (2j, 2j+1)

    const float* img = x + b * 784;
    float4 top = *reinterpret_cast<const float4*>(img + (2 * r) * 28 + 4 * j);
    float4 bot = *reinterpret_cast<const float4*>(img + (2 * r + 1) * 28 + 4 * j);

    float h0 = ph[0], h1 = ph[1], h2 = ph[2], h3 = ph[3];

    // Shifted half-angles per patch (wires 0..3), patch A = lo, patch B = hi.
    float sA0, cA0, sA1, cA1, sA2, cA2, sA3, cA3;
    float sB0, cB0, sB1, cB1, sB2, cB2, sB3, cB3;
    __sincosf(fmaf(0.5f, top.x, h0), &sA0, &cA0);
    __sincosf(fmaf(0.5f, top.y, h1), &sA1, &cA1);
    __sincosf(fmaf(0.5f, bot.x, h2), &sA2, &cA2);
    __sincosf(fmaf(0.5f, bot.y, h3), &sA3, &cA3);
    __sincosf(fmaf(0.5f, top.z, h0), &sB0, &cB0);
    __sincosf(fmaf(0.5f, top.w, h1), &sB1, &cB1);
    __sincosf(fmaf(0.5f, bot.z, h2), &sB2, &cB2);
    __sincosf(fmaf(0.5f, bot.w, h3), &sB3, &cB3);

    // Pack per-wire cos/sin across the two patches, then build the
    // product-state factors with packed muls.
    u64 C0 = pk2(cA0, cB0), S0 = pk2(sA0, sB0);
    u64 C1 = pk2(cA1, cB1), S1 = pk2(sA1, sB1);
    u64 C2 = pk2(cA2, cB2), S2 = pk2(sA2, sB2);
    u64 C3 = pk2(cA3, cB3), S3 = pk2(sA3, sB3);

    u64 A2[4], B2[4];
    A2[0] = mul2(C0, C1); A2[1] = mul2(C0, S1);
    A2[2] = mul2(S0, C1); A2[3] = mul2(S0, S1);
    B2[0] = mul2(C2, C3); B2[1] = mul2(C2, S3);
    B2[2] = mul2(S2, C3); B2[3] = mul2(S2, S3);

    // st[b0*8 + b1*4 + b2*2 + b3]; wire w <-> bit (3-w).
    u64 st[16];
    #pragma unroll
    for (int i = 0; i < 16; ++i)
        st[i] = mul2(A2[i >> 2], B2[i & 3]);

    // ---- layer-0 residual: CNOT ring (register permutation, free) ----
    #pragma unroll
    for (int i = 0; i < 16; ++i)
        if ((i & 8) && !(i & 4)) { u64 t = st[i]; st[i] = st[i | 4]; st[i | 4] = t; }
    #pragma unroll
    for (int i = 0; i < 16; ++i)
        if ((i & 4) && !(i & 2)) { u64 t = st[i]; st[i] = st[i | 2]; st[i | 2] = t; }
    #pragma unroll
    for (int i = 0; i < 16; ++i)
        if ((i & 2) && !(i & 1)) { u64 t = st[i]; st[i] = st[i | 1]; st[i | 1] = t; }
    #pragma unroll
    for (int i = 0; i < 16; ++i)
        if ((i & 1) && !(i & 8)) { u64 t = st[i]; st[i] = st[i | 8]; st[i | 8] = t; }

    // ---- layer-1 RYs via 3-shear lifting: 3 fma2 per 2x2 rotation ----
    // Butterfly rotation angle phi = theta/2:
    //   A1 = A - t*B;  B' = B + s*A1;  A' = A1 - t*B'
    // with t = tan(phi/2) = tan(theta/4), s = sin(phi) = sin(theta/2).
    #pragma unroll
    for (int w = 0; w < 4; ++w) {
        u64 nt2 = bc2(-pt[w]);
        u64 s2  = bc2(psn[w]);
        int m = 8 >> w;
        #pragma unroll
        for (int i = 0; i < 16; ++i) {
            if (!(i & m)) {
                u64 A = st[i], B = st[i | m];
                u64 A1 = fma2(nt2, B,  A);     // A - t*B
                u64 Bp = fma2(s2,  A1, B);     // s*A + cos(phi)*B
                st[i | m] = Bp;
                st[i]     = fma2(nt2, Bp, A1); // cos(phi)*A - s*B
            }
        }
    }

    // ---- layer-1 CNOT ring (free) ----
    #pragma unroll
    for (int i = 0; i < 16; ++i)
        if ((i & 8) && !(i & 4)) { u64 t = st[i]; st[i] = st[i | 4]; st[i | 4] = t; }
    #pragma unroll
    for (int i = 0; i < 16; ++i)
        if ((i & 4) && !(i & 2)) { u64 t = st[i]; st[i] = st[i | 2]; st[i | 2] = t; }
    #pragma unroll
    for (int i = 0; i < 16; ++i)
        if ((i & 2) && !(i & 1)) { u64 t = st[i]; st[i] = st[i | 1]; st[i | 1] = t; }
    #pragma unroll
    for (int i = 0; i < 16; ++i)
        if ((i & 1) && !(i & 8)) { u64 t = st[i]; st[i] = st[i | 8]; st[i | 8] = t; }

    // ---- probabilities + signed reduction tree ----
    #pragma unroll
    for (int i = 0; i < 16; ++i)
        st[i] = mul2(st[i], st[i]);

    u64 NEG = bc2(-1.0f);

    u64 e[8], d3[8];
    #pragma unroll
    for (int k = 0; k < 8; ++k) {
        e[k]  = add2(st[2 * k], st[2 * k + 1]);
        d3[k] = fma2(NEG, st[2 * k + 1], st[2 * k]);   // pr[2k] - pr[2k+1]
    }
    u64 z3 = add2(add2(add2(d3[0], d3[1]), add2(d3[2], d3[3])),
                  add2(add2(d3[4], d3[5]), add2(d3[6], d3[7])));

    u64 f[4], d2[4];
    #pragma unroll
    for (int k = 0; k < 4; ++k) {
        f[k]  = add2(e[2 * k], e[2 * k + 1]);
        d2[k] = fma2(NEG, e[2 * k + 1], e[2 * k]);
    }
    u64 z2 = add2(add2(d2[0], d2[1]), add2(d2[2], d2[3]));

    u64 u = add2(f[0], f[1]), v = add2(f[2], f[3]);
    u64 w_ = fma2(NEG, f[1], f[0]), xx = fma2(NEG, f[3], f[2]);
    u64 z1 = add2(w_, xx);
    u64 z0 = fma2(NEG, v, u);

    float4 o0, o1;
    upk2(z0, o0.x, o1.x);
    upk2(z1, o0.y, o1.y);
    upk2(z2, o0.z, o1.z);
    upk2(z3, o0.w, o1.w);

    int n0 = 2 * q;
    reinterpret_cast<float4*>(out)[n0]     = o0;
    reinterpret_cast<float4*>(out)[n0 + 1] = o1;
}

extern "C" void kernel_launch(void* const* d_in, const int* in_sizes, int n_in,
                              void* d_out, int out_size)
{
    const float* x      = (const float*)d_in[0];   // (8192,1,28,28) float32
    const float* params = (const float*)d_in[1];   // (2,4) float32
    float* out          = (float*)d_out;           // (8192, 784) float32

    (void)in_sizes; (void)n_in; (void)out_size;

    const int threads = 128;
    const int blocks  = NPAIR / threads;           // 6272, exact
    quanv5_kernel<<<blocks, threads>>>(x, params, out);
}

// round 6
// speedup vs baseline: 2.0825x; 1.3175x over previous
#include <cuda_runtime.h>

// Quanvolution quantum filter — closed-form Heisenberg-picture evaluation.
// Circuit: |0000> -RY(x+p0)-> product state -C-> -RY(p1)-> -C-> measure Z_w,
// with C = CNOT(0,1)(1,2)(2,3)(3,0). Pushing Z_w through C, R, C gives a sum
// of Pauli strings; Y-containing strings vanish on real product states, and
// <Z_v> = cos(a_v), <X_v> = sin(a_v) with a_v = x_v + params[0][v].
// Result: 4 small polynomials in {cos a_v, sin a_v}, no statevector at all.
// Two patches per thread via packed f32x2 ops.

#define BATCH   8192
#define NPATCH  196
#define NTOT    (BATCH * NPATCH)
#define NPAIR   (NTOT / 2)          // 802816 = 6272 * 128

typedef unsigned long long u64;

__device__ __forceinline__ u64 pk2(float lo, float hi) {
    u64 r; asm("mov.b64 %0, {%1, %2};" : "=l"(r) : "f"(lo), "f"(hi)); return r;
}
__device__ __forceinline__ u64 mul2(u64 a, u64 b) {
    u64 r; asm("mul.rn.f32x2 %0, %1, %2;" : "=l"(r) : "l"(a), "l"(b)); return r;
}
__device__ __forceinline__ u64 fma2(u64 a, u64 b, u64 c) {
    u64 r; asm("fma.rn.f32x2 %0, %1, %2, %3;" : "=l"(r) : "l"(a), "l"(b), "l"(c)); return r;
}
__device__ __forceinline__ void upk2(u64 v, float& lo, float& hi) {
    asm("mov.b64 {%0, %1}, %2;" : "=f"(lo), "=f"(hi) : "l"(v));
}

__global__ __launch_bounds__(128)
void quanv6_kernel(const float* __restrict__ x,
                   const float* __restrict__ params,
                   float* __restrict__ out)
{
    // P[v] = params[0][v] (full angle shift).  K[0..17] = coefficient
    // products of cos/sin of layer-1 params, pre-broadcast into both lanes.
    __shared__ u64 K[18];
    __shared__ float P[4];
    if (threadIdx.x == 0) {
        float c[4], s[4];
        #pragma unroll
        for (int v = 0; v < 4; ++v) {
            P[v] = params[v];
            __sincosf(params[4 + v], &s[v], &c[v]);
        }
        float k[18];
        k[0]  =  c[1] * c[2] * c[3];          // E0: z0z1z3
        k[1]  = -c[1] * c[2] * s[3];          // E0: x0x1z2x3
        k[2]  = -s[1] * c[2] * c[3];          // E0: x1x2z3
        k[3]  = -s[1] * s[2] * s[3];          // E0: x0
        k[4]  =  c[0] * c[1];                 // E1: z0z2z3
        k[5]  =  s[0] * s[1];                 // E1: x0x2
        k[6]  =  c[0] * c[1] * c[2];          // E2: z1z3
        k[7]  = -c[0] * s[1] * c[2];          // E2: z0x1x2z3
        k[8]  = -s[0] * c[1] * c[2];          // E2: x0x1z2
        k[9]  = -s[0] * s[1] * s[2];          // E2: x0x3
        k[10] =  c[0] * c[1] * c[2] * c[3];   // E3: z0z2
        k[11] = -c[0] * c[1] * s[2] * c[3];   // E3: z1x2x3
        k[12] =  s[0] * s[1] * c[2] * c[3];   // E3: x0x2z3
        k[13] =  s[0] * c[1] * c[2] * s[3];   // E3: z2x3
        k[14] =  c[0] * s[1] * s[2] * c[3];   // E3: z0x1x3
        k[15] = -s[0] * c[1] * s[2] * s[3];   // E3: z0z1x2
        k[16] = -c[0] * s[1] * s[2] * s[3];   // E3: x0z1z2z3
        k[17] =  s[0] * s[1] * s[2] * s[3];   // E3: x1
        #pragma unroll
        for (int i = 0; i < 18; ++i) K[i] = pk2(k[i], k[i]);
    }
    __syncthreads();

    int q = blockIdx.x * blockDim.x + threadIdx.x;   // pair index (exact grid)

    int b  = q / 98;                 // 98 patch-pairs per image
    int pp = q - b * 98;
    int r  = pp / 7;                 // patch row 0..13
    int j  = pp - r * 7;             // pair column; patches (2j, 2j+1)

    const float* img = x + b * 784;
    float4 top = *reinterpret_cast<const float4*>(img + (2 * r) * 28 + 4 * j);
    float4 bot = *reinterpret_cast<const float4*>(img + (2 * r + 1) * 28 + 4 * j);

    float P0 = P[0], P1 = P[1], P2 = P[2], P3 = P[3];

    // Full angles a_v = x_v + params[0][v]; z = cos a, xs = sin a.
    float zA0, xA0, zA1, xA1, zA2, xA2, zA3, xA3;   // patch A (lo lane)
    float zB0, xB0, zB1, xB1, zB2, xB2, zB3, xB3;   // patch B (hi lane)
    __sincosf(top.x + P0, &xA0, &zA0);
    __sincosf(top.y + P1, &xA1, &zA1);
    __sincosf(bot.x + P2, &xA2, &zA2);
    __sincosf(bot.y + P3, &xA3, &zA3);
    __sincosf(top.z + P0, &xB0, &zB0);
    __sincosf(top.w + P1, &xB1, &zB1);
    __sincosf(bot.z + P2, &xB2, &zB2);
    __sincosf(bot.w + P3, &xB3, &zB3);

    u64 Z0 = pk2(zA0, zB0), X0 = pk2(xA0, xB0);
    u64 Z1 = pk2(zA1, zB1), X1 = pk2(xA1, xB1);
    u64 Z2 = pk2(zA2, zB2), X2 = pk2(xA2, xB2);
    u64 Z3 = pk2(zA3, zB3), X3 = pk2(xA3, xB3);

    // Shared pair products.
    u64 zz01 = mul2(Z0, Z1), zz02 = mul2(Z0, Z2), zz03 = mul2(Z0, Z3);
    u64 zz13 = mul2(Z1, Z3), zz23 = mul2(Z2, Z3);
    u64 xx01 = mul2(X0, X1), xx02 = mul2(X0, X2), xx03 = mul2(X0, X3);
    u64 xx12 = mul2(X1, X2), xx13 = mul2(X1, X3), xx23 = mul2(X2, X3);
    u64 zx23 = mul2(Z2, X3);

    // E[Z_0] = k0*z0z1z3 + k1*x0x1z2x3 + k2*x1x2z3 + k3*x0
    u64 e0 = mul2(K[0], mul2(zz01, Z3));
    e0 = fma2(K[1], mul2(xx01, zx23), e0);
    e0 = fma2(K[2], mul2(xx12, Z3), e0);
    e0 = fma2(K[3], X0, e0);

    // E[Z_1] = k4*z0z2z3 + k5*x0x2
    u64 e1 = mul2(K[4], mul2(Z0, zz23));
    e1 = fma2(K[5], xx02, e1);

    // E[Z_2] = k6*z1z3 + k7*z0x1x2z3 + k8*x0x1z2 + k9*x0x3
    u64 e2 = mul2(K[6], zz13);
    e2 = fma2(K[7], mul2(xx12, zz03), e2);
    e2 = fma2(K[8], mul2(xx01, Z2), e2);
    e2 = fma2(K[9], xx03, e2);

    // E[Z_3] = k10*z0z2 + k11*z1x2x3 + k12*x0x2z3 + k13*z2x3
    //        + k14*z0x1x3 + k15*z0z1x2 + k16*x0z1z2z3 + k17*x1
    u64 e3 = mul2(K[10], zz02);
    e3 = fma2(K[11], mul2(Z1, xx23), e3);
    e3 = fma2(K[12], mul2(xx02, Z3), e3);
    e3 = fma2(K[13], zx23, e3);
    e3 = fma2(K[14], mul2(Z0, xx13), e3);
    e3 = fma2(K[15], mul2(zz01, X2), e3);
    e3 = fma2(K[16], mul2(mul2(zz13, Z2), X0), e3);
    e3 = fma2(K[17], X1, e3);

    float4 o0, o1;
    upk2(e0, o0.x, o1.x);
    upk2(e1, o0.y, o1.y);
    upk2(e2, o0.z, o1.z);
    upk2(e3, o0.w, o1.w);

    int n0 = 2 * q;
    reinterpret_cast<float4*>(out)[n0]     = o0;
    reinterpret_cast<float4*>(out)[n0 + 1] = o1;
}

extern "C" void kernel_launch(void* const* d_in, const int* in_sizes, int n_in,
                              void* d_out, int out_size)
{
    const float* x      = (const float*)d_in[0];   // (8192,1,28,28) float32
    const float* params = (const float*)d_in[1];   // (2,4) float32
    float* out          = (float*)d_out;           // (8192, 784) float32

    (void)in_sizes; (void)n_in; (void)out_size;

    const int threads = 128;
    const int blocks  = NPAIR / threads;           // 6272, exact
    quanv6_kernel<<<blocks, threads>>>(x, params, out);
}